// round 16
// baseline (speedup 1.0000x reference)
#include <cuda_runtime.h>
#include <cuda_bf16.h>
#include <math.h>

// feat_rgb: [B=4, C=256, IH=128, IW=512] fp32
// out:      [4, 256, BEV_H=128, BEV_W=512] fp32
#define BEV_H 128
#define BEV_W 512
#define IH    128
#define IW    512
#define NB    4
#define NC    256
#define PLANE (IH * IW)
#define OPLANE (BEV_H * BEV_W)
#define CHUNK 64                   // channels per thread (4 batches of 16)
#define BATCH 16                   // unrolled immediate-offset batch (R13 proven)
#define NCG   (NC / CHUNK)         // 4 channel groups -> 4x math redundancy

#define TWO_PI_F   6.2831853071795864769f
#define PI_F       3.1415926535897932385f
#define HALF_PI_F  1.5707963267948966192f

// Bit-exact replacements for mod2pi = fmodf(x, 2pi) + (neg ? +2pi : 0),
// valid for the argument ranges proven at each call site:
//  - |x| < 2pi : fmodf(x,2pi) == x exactly  -> conditional add only
//  - x in [2pi, 4pi): fmodf == x - 2pi, and fl(x - 2pi) is exact (Sterbenz)

__global__ void __launch_bounds__(128, 9)
bev_fused_kernel(const float* __restrict__ feat,
                 const float* __restrict__ rot,
                 const float* __restrict__ shift_u,
                 const float* __restrict__ shift_v,
                 const float* __restrict__ mpp,
                 float* __restrict__ out)
{
    int t = blockIdx.x * blockDim.x + threadIdx.x;
    // layout: [b][cg][i][j], j fastest -> warp = 32 consecutive j (critical)
    int j  = t & (BEV_W - 1);
    int i  = (t >> 9) & (BEV_H - 1);
    int cg = (t >> 16) & (NCG - 1);
    int b  = t >> 18;

    const float r  = rot[b];
    const float su = shift_u[b];
    const float sv = shift_v[b];
    const float m  = mpp[0];

    // --- inline coordinates (bit-exact vs reference) ---
    float center_v = (float)BEV_H * 0.5f - 0.5f + sv;
    float center_u = (float)BEV_W * 0.5f - 0.5f + su;
    float dy = (float)i - center_v;
    float dx = (float)j - center_u;
    float radius = sqrtf(dy * dy + dx * dx);

    float theta = atan2f(dy, dx);                 // [-pi, pi]
    if (theta < 0.0f) theta += TWO_PI_F;          // mod2pi #1 (|x| < 2pi)
    float s = -HALF_PI_F + theta;                 // (-pi/2, 2pi)
    if (s < 0.0f) s += TWO_PI_F;                  // mod2pi #2 (|x| < 2pi)
    float s2 = s + r * TWO_PI_F;                  // (-2pi, 4pi)
    if (s2 >= TWO_PI_F)      s2 -= TWO_PI_F;      // mod2pi #3 (Sterbenz-exact)
    else if (s2 < 0.0f)      s2 += TWO_PI_F;
    float u = s2 / TWO_PI_F * (float)IW;

    float dist = radius * m;
    float phi  = atan2f(dist, -2.0f);             // GRD_HEIGHT = -2.0
    float v    = phi / PI_F * (float)IH;

    float fx = floorf(u);
    float fy = floorf(v);
    float x0 = fminf(fmaxf(fx,        0.0f), (float)(IW - 1));
    float x1 = fminf(fmaxf(fx + 1.0f, 0.0f), (float)(IW - 1));
    float y0 = fminf(fmaxf(fy,        0.0f), (float)(IH - 1));
    float y1 = fminf(fmaxf(fy + 1.0f, 0.0f), (float)(IH - 1));

    float w_nw = (x1 - u) * (y1 - v);
    float w_ne = (u - x0) * (y1 - v);
    float w_sw = (x1 - u) * (v - y0);
    float w_se = (u - x0) * (v - y0);

    int ix0 = (int)x0, ix1 = (int)x1, iy0 = (int)y0, iy1 = (int)y1;
    int i00 = iy0 * IW + ix0;
    int i01 = iy0 * IW + ix1;
    int i10 = iy1 * IW + ix0;
    int i11 = iy1 * IW + ix1;

    // --- gather loop: 4 batches of 16 immediate-offset channels ---
    int c0 = cg * CHUNK;
    const float* __restrict__ p  = feat + (size_t)(b * NC + c0) * PLANE;
    const float* __restrict__ pa = p + i00;
    const float* __restrict__ pb = p + i01;
    const float* __restrict__ pc = p + i10;
    const float* __restrict__ pd = p + i11;
    float* __restrict__ o = out + (size_t)((b * NC + c0) * BEV_H + i) * BEV_W + j;

    #pragma unroll 1
    for (int g = 0; g < CHUNK / BATCH; ++g) {
        #pragma unroll
        for (int c = 0; c < BATCH; ++c) {
            float a00 = __ldg(pa + c * PLANE);
            float a01 = __ldg(pb + c * PLANE);
            float a10 = __ldg(pc + c * PLANE);
            float a11 = __ldg(pd + c * PLANE);
            o[c * OPLANE] = a00 * w_nw + a01 * w_ne + a10 * w_sw + a11 * w_se;
        }
        pa += (size_t)BATCH * PLANE;
        pb += (size_t)BATCH * PLANE;
        pc += (size_t)BATCH * PLANE;
        pd += (size_t)BATCH * PLANE;
        o  += (size_t)BATCH * OPLANE;
    }
}

extern "C" void kernel_launch(void* const* d_in, const int* in_sizes, int n_in,
                              void* d_out, int out_size)
{
    const float* feat    = (const float*)d_in[0];
    const float* rot     = (const float*)d_in[1];
    const float* shift_u = (const float*)d_in[2];
    const float* shift_v = (const float*)d_in[3];
    const float* mpp     = (const float*)d_in[4];
    float* out = (float*)d_out;

    int total = NB * NCG * BEV_H * BEV_W;   // 1,048,576 threads
    bev_fused_kernel<<<total / 128, 128>>>(feat, rot, shift_u, shift_v, mpp, out);
}

// round 17
// speedup vs baseline: 1.0869x; 1.0869x over previous
#include <cuda_runtime.h>
#include <cuda_bf16.h>
#include <math.h>

// feat_rgb: [B=4, C=256, IH=128, IW=512] fp32
// out:      [4, 256, BEV_H=128, BEV_W=512] fp32
#define BEV_H 128
#define BEV_W 512
#define IH    128
#define IW    512
#define NB    4
#define NC    256
#define PLANE (IH * IW)
#define OPLANE (BEV_H * BEV_W)
#define NPIX  (NB * BEV_H * BEV_W)     // 262144
#define CHUNK 16                       // channels per thread (fully unrolled)
#define NCH   (NC / CHUNK)             // 16

#define TWO_PI_F   6.2831853071795864769f
#define PI_F       3.1415926535897932385f
#define HALF_PI_F  1.5707963267948966192f

// Interleaved 32B sampling record: idx + weights share one 128B line group
// (4 records per line, never straddling) -> B's two record loads cost one
// L2 round trip instead of two.
struct __align__(32) Rec {
    int4   idx;   // i00, i01, i10, i11
    float4 w;     // w_nw, w_ne, w_sw, w_se
};
__device__ Rec g_rec[NPIX];   // 8 MB, L2-resident

__device__ __forceinline__ float mod2pi(float x) {
    float m = fmodf(x, TWO_PI_F);
    if (m < 0.0f) m += TWO_PI_F;
    return m;
}

// ---------------- Kernel A: coordinates -> records (once per pixel) --------
__global__ void __launch_bounds__(256)
bev_coords_kernel(const float* __restrict__ rot,
                  const float* __restrict__ shift_u,
                  const float* __restrict__ shift_v,
                  const float* __restrict__ mpp)
{
    int t = blockIdx.x * blockDim.x + threadIdx.x;   // [b][i][j], j fastest
    int j = t & (BEV_W - 1);
    int i = (t >> 9) & (BEV_H - 1);
    int b = t >> 16;

    const float r  = rot[b];
    const float su = shift_u[b];
    const float sv = shift_v[b];
    const float m  = mpp[0];

    float center_v = (float)BEV_H * 0.5f - 0.5f + sv;
    float center_u = (float)BEV_W * 0.5f - 0.5f + su;
    float dy = (float)i - center_v;
    float dx = (float)j - center_u;
    float radius = sqrtf(dy * dy + dx * dx);

    float theta = atan2f(dy, dx);
    theta = mod2pi(-HALF_PI_F + mod2pi(theta));
    theta = mod2pi(theta + r * TWO_PI_F);
    float u = theta / TWO_PI_F * (float)IW;

    float dist = radius * m;
    float phi  = atan2f(dist, -2.0f);
    float v    = phi / PI_F * (float)IH;

    float fx = floorf(u);
    float fy = floorf(v);
    float x0 = fminf(fmaxf(fx,        0.0f), (float)(IW - 1));
    float x1 = fminf(fmaxf(fx + 1.0f, 0.0f), (float)(IW - 1));
    float y0 = fminf(fmaxf(fy,        0.0f), (float)(IH - 1));
    float y1 = fminf(fmaxf(fy + 1.0f, 0.0f), (float)(IH - 1));

    float4 w;
    w.x = (x1 - u) * (y1 - v);   // w_nw
    w.y = (u - x0) * (y1 - v);   // w_ne
    w.z = (x1 - u) * (v - y0);   // w_sw
    w.w = (u - x0) * (v - y0);   // w_se

    int ix0 = (int)x0, ix1 = (int)x1, iy0 = (int)y0, iy1 = (int)y1;
    int4 idx;
    idx.x = iy0 * IW + ix0;
    idx.y = iy0 * IW + ix1;
    idx.z = iy1 * IW + ix0;
    idx.w = iy1 * IW + ix1;

    g_rec[t].idx = idx;
    g_rec[t].w   = w;

    // PDL: this block's records are written; allow dependent kernel to launch.
    asm volatile("griddepcontrol.launch_dependents;");
}

// ---------------- Kernel B: gather + blend, full unroll w/ imm offsets -----
// R13 champion configuration: CHUNK 16, block 256, launch_bounds(256,5).
__global__ void __launch_bounds__(256, 5)
bev_sample_kernel(const float* __restrict__ feat,
                  float* __restrict__ out)
{
    int t = blockIdx.x * blockDim.x + threadIdx.x;
    // layout: [b][cc][i][j], j fastest -> warp = 32 consecutive j (critical)
    int j  = t & (BEV_W - 1);
    int i  = (t >> 9) & (BEV_H - 1);
    int cc = (t >> 16) & (NCH - 1);
    int b  = t >> 20;

    int rec = (b << 16) | (i << 9) | j;          // record index (channel-free)

    // PDL: integer preamble above overlaps kernel A's tail; wait before
    // touching A's output.
    asm volatile("griddepcontrol.wait;");

    const int4   idx = g_rec[rec].idx;
    const float4 w   = g_rec[rec].w;

    int c0 = cc * CHUNK;
    // Four corner base pointers: all subsequent accesses use compile-time
    // immediate offsets (c*PLANE*4 <= 3,932,160 B < 2^23 -> LDG [R+imm]).
    const float* __restrict__ p  = feat + (size_t)(b * NC + c0) * PLANE;
    const float* __restrict__ pa = p + idx.x;
    const float* __restrict__ pb = p + idx.y;
    const float* __restrict__ pc = p + idx.z;
    const float* __restrict__ pd = p + idx.w;
    float* __restrict__ o = out + (size_t)((b * NC + c0) * BEV_H + i) * BEV_W + j;

    #pragma unroll
    for (int c = 0; c < CHUNK; ++c) {
        float a00 = __ldg(pa + c * PLANE);
        float a01 = __ldg(pb + c * PLANE);
        float a10 = __ldg(pc + c * PLANE);
        float a11 = __ldg(pd + c * PLANE);
        o[c * OPLANE] = a00 * w.x + a01 * w.y + a10 * w.z + a11 * w.w;
    }
}

extern "C" void kernel_launch(void* const* d_in, const int* in_sizes, int n_in,
                              void* d_out, int out_size)
{
    const float* feat    = (const float*)d_in[0];
    const float* rot     = (const float*)d_in[1];
    const float* shift_u = (const float*)d_in[2];
    const float* shift_v = (const float*)d_in[3];
    const float* mpp     = (const float*)d_in[4];
    float* out = (float*)d_out;

    // Kernel A: one thread per (b, pixel)
    bev_coords_kernel<<<NPIX / 256, 256>>>(rot, shift_u, shift_v, mpp);

    // Kernel B with programmatic dependent launch: overlaps A's tail.
    int total = NB * NCH * BEV_H * BEV_W;   // 4,194,304

    cudaLaunchConfig_t cfg = {};
    cfg.gridDim  = dim3(total / 256, 1, 1);
    cfg.blockDim = dim3(256, 1, 1);
    cfg.dynamicSmemBytes = 0;
    cudaLaunchAttribute attrs[1];
    attrs[0].id = cudaLaunchAttributeProgrammaticStreamSerialization;
    attrs[0].val.programmaticStreamSerializationAllowed = 1;
    cfg.attrs = attrs;
    cfg.numAttrs = 1;

    cudaLaunchKernelEx(&cfg, bev_sample_kernel, feat, out);
}